// round 1
// baseline (speedup 1.0000x reference)
#include <cuda_runtime.h>

// Problem constants (fixed by the dataset)
#define NN 20000
#define EE 320000
#define DD 128
#define KK 8
#define HH 64
#define KHD 512   // K*H

// ---------------- scratch (__device__ globals; no allocations) -------------
__device__ float g_x[(size_t)EE * DD];      // mean edge features (E,128)  164 MB
__device__ float g_e[EE * KK];              // leaky-relu logits (E,8)
__device__ float g_er[NN * KK];             // node_feat @ W_r^T
__device__ float g_v[DD * KK];              // W_enc folded with attn_l
__device__ float g_y[(size_t)NN * KK * DD]; // per-node weighted x sums (N,8,128) 82 MB
__device__ int   g_cnt[NN];
__device__ int   g_off[NN];
__device__ int   g_cur[NN];
__device__ int   g_perm[EE];

// ---------------- CSR build ------------------------------------------------
__global__ void zero_kernel() {
    int i = blockIdx.x * blockDim.x + threadIdx.x;
    if (i < NN) g_cnt[i] = 0;
}

__global__ void count_kernel(const int* __restrict__ dst) {
    int e = blockIdx.x * blockDim.x + threadIdx.x;
    if (e < EE) atomicAdd(&g_cnt[dst[e]], 1);
}

// single-block exclusive scan over 20000 counts (1024 threads x 20 chunk)
__global__ void scan_kernel() {
    __shared__ int s[1024];
    const int CH = 20; // 1024*20 = 20480 >= NN
    int tid = threadIdx.x;
    int start = tid * CH;
    int lsum = 0;
    for (int i = 0; i < CH; i++) {
        int idx = start + i;
        if (idx < NN) lsum += g_cnt[idx];
    }
    s[tid] = lsum;
    __syncthreads();
    for (int o = 1; o < 1024; o <<= 1) {
        int v = (tid >= o) ? s[tid - o] : 0;
        __syncthreads();
        s[tid] += v;
        __syncthreads();
    }
    int run = s[tid] - lsum; // exclusive prefix for this thread's chunk
    for (int i = 0; i < CH; i++) {
        int idx = start + i;
        if (idx < NN) {
            g_off[idx] = run;
            g_cur[idx] = run;
            run += g_cnt[idx];
        }
    }
}

__global__ void fill_kernel(const int* __restrict__ dst) {
    int e = blockIdx.x * blockDim.x + threadIdx.x;
    if (e < EE) {
        int pos = atomicAdd(&g_cur[dst[e]], 1);
        g_perm[pos] = e;
    }
}

// ---------------- small precomputes ---------------------------------------
// v[d,k] = sum_h W_enc[d, k*H+h] * attn_l[k,h]
__global__ void v_kernel(const float* __restrict__ W_enc,
                         const float* __restrict__ attn_l) {
    int i = threadIdx.x;          // 1024 threads = 128*8
    int d = i >> 3, k = i & 7;
    float s = 0.f;
    #pragma unroll 8
    for (int h = 0; h < HH; h++)
        s += W_enc[(size_t)d * KHD + k * HH + h] * attn_l[k * HH + h];
    g_v[d * KK + k] = s;
}

// er[n,k] = sum_d node_feat[n,d] * W_r[k,d]   (one warp per node)
__global__ void er_kernel(const float* __restrict__ nf,
                          const float* __restrict__ W_r) {
    int w = threadIdx.x >> 5;
    int lane = threadIdx.x & 31;
    int n = blockIdx.x * 8 + w;
    if (n >= NN) return;
    const float* row = nf + (size_t)n * DD;
    float a0 = row[lane], a1 = row[lane + 32], a2 = row[lane + 64], a3 = row[lane + 96];
    #pragma unroll
    for (int k = 0; k < KK; k++) {
        const float* wr = W_r + k * DD;
        float v = a0 * wr[lane] + a1 * wr[lane + 32] + a2 * wr[lane + 64] + a3 * wr[lane + 96];
        #pragma unroll
        for (int o = 16; o > 0; o >>= 1) v += __shfl_xor_sync(0xffffffffu, v, o);
        if (lane == 0) g_er[n * KK + k] = v;
    }
}

// ---------------- edge pass: x = mean_l ef, logits ------------------------
// 256 threads = 2 edges x 128 threads
__global__ void edge_kernel(const float* __restrict__ ef,
                            const int* __restrict__ dst) {
    __shared__ float s_v[DD * 9];          // padded (9) for conflict-free reads
    __shared__ float s_red[2][4][KK];
    for (int i = threadIdx.x; i < DD * KK; i += blockDim.x) {
        int d = i / KK, k = i % KK;
        s_v[d * 9 + k] = g_v[i];
    }
    __syncthreads();

    int sub = threadIdx.x >> 7;            // which edge in block
    int t = threadIdx.x & 127;             // feature index
    int edge = blockIdx.x * 2 + sub;       // EE even -> always valid
    const float* base = ef + (size_t)edge * (3 * DD);
    float x = (base[t] + base[t + DD] + base[t + 2 * DD]) * (1.0f / 3.0f);
    g_x[(size_t)edge * DD + t] = x;

    float pk[KK];
    #pragma unroll
    for (int k = 0; k < KK; k++) pk[k] = x * s_v[t * 9 + k];
    #pragma unroll
    for (int k = 0; k < KK; k++) {
        float v = pk[k];
        #pragma unroll
        for (int o = 16; o > 0; o >>= 1) v += __shfl_xor_sync(0xffffffffu, v, o);
        if ((t & 31) == 0) s_red[sub][t >> 5][k] = v;
    }
    __syncthreads();
    if (t < KK) {
        float el = s_red[sub][0][t] + s_red[sub][1][t] + s_red[sub][2][t] + s_red[sub][3][t];
        float z = el + g_er[dst[edge] * KK + t];
        g_e[edge * KK + t] = (z > 0.f) ? z : 0.01f * z;  // leaky relu
    }
}

// ---------------- per-node softmax + weighted x aggregation ---------------
// one block (256 threads) per node; thread owns 4 of the 1024 y-values
__global__ void node_kernel() {
    int n = blockIdx.x;
    int tid = threadIdx.x;
    __shared__ float s_m[KK], s_is[KK];
    __shared__ float s_a[8][KK];
    __shared__ int   s_eidx[8];

    int deg = g_cnt[n];
    int off = g_off[n];
    float acc[4] = {0.f, 0.f, 0.f, 0.f};

    if (deg > 0) {
        if (tid < KK) {
            int k = tid;
            float m = -1e30f;
            for (int i = 0; i < deg; i++) {
                int e = g_perm[off + i];
                m = fmaxf(m, g_e[e * KK + k]);
            }
            float s = 0.f;
            for (int i = 0; i < deg; i++) {
                int e = g_perm[off + i];
                s += __expf(g_e[e * KK + k] - m);
            }
            s_m[k] = m;
            s_is[k] = 1.0f / s;
        }
        __syncthreads();

        int d = tid & 127;
        int k0 = tid >> 7;   // 0 or 1; owned k's: k0, k0+2, k0+4, k0+6
        for (int b = 0; b < deg; b += 8) {
            int cnt = min(8, deg - b);
            if (tid < cnt * KK) {
                int ii = tid >> 3, k = tid & 7;
                int e = g_perm[off + b + ii];
                if (k == 0) s_eidx[ii] = e;
                s_a[ii][k] = __expf(g_e[e * KK + k] - s_m[k]) * s_is[k];
            }
            __syncthreads();
            for (int ii = 0; ii < cnt; ii++) {
                int e = s_eidx[ii];
                float xd = g_x[(size_t)e * DD + d];
                #pragma unroll
                for (int j = 0; j < 4; j++) acc[j] += xd * s_a[ii][k0 + 2 * j];
            }
            __syncthreads();
        }
    }
    size_t ybase = (size_t)n * (KK * DD);
    #pragma unroll
    for (int j = 0; j < 4; j++) g_y[ybase + tid + 256 * j] = acc[j];
}

// ---------------- block-diagonal GEMM: out[n,k,:] = y[n,k,:] @ W_k --------
// grid (ceil(N/64), 8); block 256; 64x64 tile, BK=32, 4x4 per-thread microtile
__global__ void out_kernel(const float* __restrict__ W_enc,
                           float* __restrict__ out) {
    __shared__ float As[64][33];
    __shared__ float Ws[32][65];
    int k = blockIdx.y;
    int n0 = blockIdx.x * 64;
    int tid = threadIdx.x;
    int tx = tid & 15, ty = tid >> 4;
    float c[4][4] = {};

    for (int kk = 0; kk < DD; kk += 32) {
        #pragma unroll
        for (int p = 0; p < 8; p++) {
            int q = tid + 256 * p;
            int row = q >> 5, d = q & 31;
            int n = n0 + row;
            As[row][d] = (n < NN) ? g_y[(size_t)n * (KK * DD) + k * DD + kk + d] : 0.f;
        }
        #pragma unroll
        for (int p = 0; p < 8; p++) {
            int q = tid + 256 * p;
            int d = q >> 6, h = q & 63;
            Ws[d][h] = W_enc[(size_t)(kk + d) * KHD + k * HH + h];
        }
        __syncthreads();
        #pragma unroll
        for (int d = 0; d < 32; d++) {
            float a[4], b[4];
            #pragma unroll
            for (int r = 0; r < 4; r++) a[r] = As[ty * 4 + r][d];
            #pragma unroll
            for (int cc = 0; cc < 4; cc++) b[cc] = Ws[d][tx * 4 + cc];
            #pragma unroll
            for (int r = 0; r < 4; r++)
                #pragma unroll
                for (int cc = 0; cc < 4; cc++) c[r][cc] += a[r] * b[cc];
        }
        __syncthreads();
    }
    #pragma unroll
    for (int r = 0; r < 4; r++) {
        int n = n0 + ty * 4 + r;
        if (n < NN) {
            #pragma unroll
            for (int cc = 0; cc < 4; cc++)
                out[(size_t)n * KHD + k * HH + tx * 4 + cc] = c[r][cc];
        }
    }
}

// ---------------- launch ---------------------------------------------------
extern "C" void kernel_launch(void* const* d_in, const int* in_sizes, int n_in,
                              void* d_out, int out_size) {
    const float* node_feat = (const float*)d_in[0]; // (N,128)
    const float* edge_feat = (const float*)d_in[1]; // (E,3,128)
    const float* W_enc     = (const float*)d_in[2]; // (128,512)
    const float* attn_l    = (const float*)d_in[3]; // (1,8,64)
    const float* W_r       = (const float*)d_in[4]; // (8,128)
    const int*   dst       = (const int*)d_in[5];   // (E,)
    float* out = (float*)d_out;                     // (N,8,64)

    zero_kernel<<<(NN + 255) / 256, 256>>>();
    count_kernel<<<(EE + 255) / 256, 256>>>(dst);
    scan_kernel<<<1, 1024>>>();
    fill_kernel<<<(EE + 255) / 256, 256>>>(dst);

    v_kernel<<<1, 1024>>>(W_enc, attn_l);
    er_kernel<<<(NN + 7) / 8, 256>>>(node_feat, W_r);

    edge_kernel<<<EE / 2, 256>>>(edge_feat, dst);
    node_kernel<<<NN, 256>>>();
    out_kernel<<<dim3((NN + 63) / 64, 8), 256>>>(W_enc, out);
}

// round 2
// speedup vs baseline: 1.0055x; 1.0055x over previous
#include <cuda_runtime.h>

// Problem constants (fixed by the dataset)
#define NN 20000
#define EE 320000
#define DD 128
#define KK 8
#define HH 64
#define KHD 512   // K*H

// ---------------- scratch (__device__ globals; no allocations) -------------
__device__ float g_x[(size_t)EE * DD];      // mean edge features (E,128)
__device__ float g_w[EE * KK];              // exp(leakyrelu(logit))
__device__ float g_er[NN * KK];             // node_feat @ W_r^T
__device__ float g_v[DD * KK];              // W_enc folded with attn_l
__device__ float g_denom[NN * KK];          // softmax denominators
__device__ float g_y[(size_t)NN * KK * DD]; // per-node weighted x sums (N,8,128)
__device__ int   g_cnt[NN];
__device__ int   g_off[NN];
__device__ int   g_cur[NN];
__device__ int   g_perm[EE];

// ---------------- zero counters + denominators -----------------------------
__global__ void zero_kernel() {
    int i = blockIdx.x * blockDim.x + threadIdx.x;
    if (i < NN) g_cnt[i] = 0;
    if (i < NN * KK) g_denom[i] = 0.f;
}

__global__ void count_kernel(const int* __restrict__ dst) {
    int e = blockIdx.x * blockDim.x + threadIdx.x;
    if (e < EE) atomicAdd(&g_cnt[dst[e]], 1);
}

// single-block exclusive scan over 20000 counts (1024 threads x 20 chunk)
__global__ void scan_kernel() {
    __shared__ int s[1024];
    const int CH = 20;
    int tid = threadIdx.x;
    int start = tid * CH;
    int lsum = 0;
    for (int i = 0; i < CH; i++) {
        int idx = start + i;
        if (idx < NN) lsum += g_cnt[idx];
    }
    s[tid] = lsum;
    __syncthreads();
    for (int o = 1; o < 1024; o <<= 1) {
        int v = (tid >= o) ? s[tid - o] : 0;
        __syncthreads();
        s[tid] += v;
        __syncthreads();
    }
    int run = s[tid] - lsum;
    for (int i = 0; i < CH; i++) {
        int idx = start + i;
        if (idx < NN) {
            g_off[idx] = run;
            g_cur[idx] = run;
            run += g_cnt[idx];
        }
    }
}

__global__ void fill_kernel(const int* __restrict__ dst) {
    int e = blockIdx.x * blockDim.x + threadIdx.x;
    if (e < EE) {
        int pos = atomicAdd(&g_cur[dst[e]], 1);
        g_perm[pos] = e;
    }
}

// ---------------- small precomputes ---------------------------------------
// v[d,k] = sum_h W_enc[d, k*H+h] * attn_l[k,h]
__global__ void v_kernel(const float* __restrict__ W_enc,
                         const float* __restrict__ attn_l) {
    int i = threadIdx.x;          // 1024 threads = 128*8
    int d = i >> 3, k = i & 7;
    float s = 0.f;
    #pragma unroll 8
    for (int h = 0; h < HH; h++)
        s += W_enc[(size_t)d * KHD + k * HH + h] * attn_l[k * HH + h];
    g_v[d * KK + k] = s;
}

// er[n,k] = sum_d node_feat[n,d] * W_r[k,d]   (one warp per node)
__global__ void er_kernel(const float* __restrict__ nf,
                          const float* __restrict__ W_r) {
    int w = threadIdx.x >> 5;
    int lane = threadIdx.x & 31;
    int n = blockIdx.x * 8 + w;
    if (n >= NN) return;
    const float* row = nf + (size_t)n * DD;
    float a0 = row[lane], a1 = row[lane + 32], a2 = row[lane + 64], a3 = row[lane + 96];
    #pragma unroll
    for (int k = 0; k < KK; k++) {
        const float* wr = W_r + k * DD;
        float v = a0 * wr[lane] + a1 * wr[lane + 32] + a2 * wr[lane + 64] + a3 * wr[lane + 96];
        #pragma unroll
        for (int o = 16; o > 0; o >>= 1) v += __shfl_xor_sync(0xffffffffu, v, o);
        if (lane == 0) g_er[n * KK + k] = v;
    }
}

// ---------------- edge pass ------------------------------------------------
// 256 threads = 2 edges x 128 threads.
// Phase 1: each thread computes one x element (mean over L=3), stages to smem.
// Phase 2: warp w (of 4 per edge) reduces k = {2w, 2w+1} over 128 dims
//          (10 shuffles/thread), applies leaky-relu + exp, stores w and
//          atomically accumulates the softmax denominator.
__global__ void edge_kernel(const float* __restrict__ ef,
                            const int* __restrict__ dst) {
    __shared__ float s_v[KK * DD];         // [k][d]
    __shared__ float s_x[2][DD];
    for (int i = threadIdx.x; i < DD * KK; i += blockDim.x) {
        int d = i >> 3, k = i & 7;
        s_v[k * DD + d] = g_v[i];          // transpose to [k][d]
    }
    __syncthreads();

    int sub = threadIdx.x >> 7;            // which edge in block
    int t = threadIdx.x & 127;             // feature index
    int edge = blockIdx.x * 2 + sub;       // EE even -> always valid
    const float* base = ef + (size_t)edge * (3 * DD);
    float x = (base[t] + base[t + DD] + base[t + 2 * DD]) * (1.0f / 3.0f);
    g_x[(size_t)edge * DD + t] = x;
    s_x[sub][t] = x;
    __syncthreads();

    int w2 = t >> 5;                       // warp within edge: 0..3
    int lane = t & 31;
    float x0 = s_x[sub][lane], x1 = s_x[sub][lane + 32],
          x2 = s_x[sub][lane + 64], x3 = s_x[sub][lane + 96];
    int nd = dst[edge];
    #pragma unroll
    for (int j = 0; j < 2; j++) {
        int k = 2 * w2 + j;
        const float* vk = s_v + k * DD;
        float v = x0 * vk[lane] + x1 * vk[lane + 32] + x2 * vk[lane + 64] + x3 * vk[lane + 96];
        #pragma unroll
        for (int o = 16; o > 0; o >>= 1) v += __shfl_xor_sync(0xffffffffu, v, o);
        if (lane == 0) {
            float z = v + g_er[nd * KK + k];
            z = (z > 0.f) ? z : 0.01f * z;          // leaky relu
            float wv = __expf(z);                    // shift-free softmax weight
            g_w[edge * KK + k] = wv;
            atomicAdd(&g_denom[nd * KK + k], wv);
        }
    }
}

// ---------------- per-node weighted x aggregation --------------------------
// one block (256 threads) per node; thread owns (d = tid&127, k = k0+2j).
// No syncthreads in the loop: perm/w reads are uniform-address broadcasts.
__global__ void node_kernel() {
    int n = blockIdx.x;
    int tid = threadIdx.x;
    __shared__ float s_inv[KK];

    int deg = g_cnt[n];
    int off = g_off[n];
    float acc[4] = {0.f, 0.f, 0.f, 0.f};

    if (tid < KK) {
        float dnm = g_denom[n * KK + tid];
        s_inv[tid] = (deg > 0) ? 1.0f / dnm : 0.f;
    }
    __syncthreads();

    int d = tid & 127;
    int k0 = tid >> 7;   // owned k's: k0, k0+2, k0+4, k0+6
    float inv[4];
    #pragma unroll
    for (int j = 0; j < 4; j++) inv[j] = s_inv[k0 + 2 * j];

    int i = 0;
    for (; i + 2 <= deg; i += 2) {
        int e0 = g_perm[off + i];
        int e1 = g_perm[off + i + 1];
        float xd0 = g_x[(size_t)e0 * DD + d];
        float xd1 = g_x[(size_t)e1 * DD + d];
        #pragma unroll
        for (int j = 0; j < 4; j++) {
            acc[j] += (g_w[e0 * KK + k0 + 2 * j] * inv[j]) * xd0;
            acc[j] += (g_w[e1 * KK + k0 + 2 * j] * inv[j]) * xd1;
        }
    }
    if (i < deg) {
        int e0 = g_perm[off + i];
        float xd0 = g_x[(size_t)e0 * DD + d];
        #pragma unroll
        for (int j = 0; j < 4; j++)
            acc[j] += (g_w[e0 * KK + k0 + 2 * j] * inv[j]) * xd0;
    }

    // y layout (n, k, d): thread (d, k0+2j) -> offset (k0+2j)*128 + d
    size_t ybase = (size_t)n * (KK * DD);
    #pragma unroll
    for (int j = 0; j < 4; j++) g_y[ybase + (size_t)(k0 + 2 * j) * DD + d] = acc[j];
}

// ---------------- block-diagonal GEMM: out[n,k,:] = y[n,k,:] @ W_k --------
__global__ void out_kernel(const float* __restrict__ W_enc,
                           float* __restrict__ out) {
    __shared__ float As[64][33];
    __shared__ float Ws[32][65];
    int k = blockIdx.y;
    int n0 = blockIdx.x * 64;
    int tid = threadIdx.x;
    int tx = tid & 15, ty = tid >> 4;
    float c[4][4] = {};

    for (int kk = 0; kk < DD; kk += 32) {
        #pragma unroll
        for (int p = 0; p < 8; p++) {
            int q = tid + 256 * p;
            int row = q >> 5, d = q & 31;
            int n = n0 + row;
            As[row][d] = (n < NN) ? g_y[(size_t)n * (KK * DD) + k * DD + kk + d] : 0.f;
        }
        #pragma unroll
        for (int p = 0; p < 8; p++) {
            int q = tid + 256 * p;
            int d = q >> 6, h = q & 63;
            Ws[d][h] = W_enc[(size_t)(kk + d) * KHD + k * HH + h];
        }
        __syncthreads();
        #pragma unroll
        for (int d = 0; d < 32; d++) {
            float a[4], b[4];
            #pragma unroll
            for (int r = 0; r < 4; r++) a[r] = As[ty * 4 + r][d];
            #pragma unroll
            for (int cc = 0; cc < 4; cc++) b[cc] = Ws[d][tx * 4 + cc];
            #pragma unroll
            for (int r = 0; r < 4; r++)
                #pragma unroll
                for (int cc = 0; cc < 4; cc++) c[r][cc] += a[r] * b[cc];
        }
        __syncthreads();
    }
    #pragma unroll
    for (int r = 0; r < 4; r++) {
        int n = n0 + ty * 4 + r;
        if (n < NN) {
            #pragma unroll
            for (int cc = 0; cc < 4; cc++)
                out[(size_t)n * KHD + k * HH + tx * 4 + cc] = c[r][cc];
        }
    }
}

// ---------------- launch ----------------------------------------------------
// Order chosen so edge_kernel is my launch index 3 -> it's the one ncu
// captures (harness prepends ~2 launches; capture = overall launch #5).
extern "C" void kernel_launch(void* const* d_in, const int* in_sizes, int n_in,
                              void* d_out, int out_size) {
    const float* node_feat = (const float*)d_in[0]; // (N,128)
    const float* edge_feat = (const float*)d_in[1]; // (E,3,128)
    const float* W_enc     = (const float*)d_in[2]; // (128,512)
    const float* attn_l    = (const float*)d_in[3]; // (1,8,64)
    const float* W_r       = (const float*)d_in[4]; // (8,128)
    const int*   dst       = (const int*)d_in[5];   // (E,)
    float* out = (float*)d_out;                     // (N,8,64)

    v_kernel<<<1, 1024>>>(W_enc, attn_l);                      // 0
    er_kernel<<<(NN + 7) / 8, 256>>>(node_feat, W_r);          // 1
    zero_kernel<<<(NN * KK + 255) / 256, 256>>>();             // 2
    edge_kernel<<<EE / 2, 256>>>(edge_feat, dst);              // 3  <- profiled
    count_kernel<<<(EE + 255) / 256, 256>>>(dst);              // 4
    scan_kernel<<<1, 1024>>>();                                // 5
    fill_kernel<<<(EE + 255) / 256, 256>>>(dst);               // 6
    node_kernel<<<NN, 256>>>();                                // 7
    out_kernel<<<dim3((NN + 63) / 64, 8), 256>>>(W_enc, out);  // 8
}

// round 3
// speedup vs baseline: 1.2650x; 1.2580x over previous
#include <cuda_runtime.h>

// Problem constants (fixed by the dataset)
#define NN 20000
#define EE 320000
#define DD 128
#define KK 8
#define HH 64
#define KHD 512   // K*H

// ---------------- scratch (__device__ globals; no allocations) -------------
// NOTE: g_cnt and g_denom are zeroed at module load and re-zeroed at the END
// of node_kernel each run, so every graph replay starts from a clean state.
__device__ float g_x[(size_t)EE * DD];      // mean edge features (E,128)
__device__ float g_w[EE * KK];              // exp(leakyrelu(logit))
__device__ float g_er[NN * KK];             // node_feat @ W_r^T
__device__ float g_v[DD * KK];              // W_enc folded with attn_l
__device__ float g_denom[NN * KK];          // softmax denominators
__device__ float g_y[(size_t)NN * KK * DD]; // per-node weighted x sums (N,8,128)
__device__ int   g_cnt[NN];
__device__ int   g_off[NN];
__device__ int   g_cur[NN];
__device__ int   g_perm[EE];

// ---------------- CSR build ------------------------------------------------
__global__ void count_kernel(const int* __restrict__ dst) {
    int e = blockIdx.x * blockDim.x + threadIdx.x;
    if (e < EE) atomicAdd(&g_cnt[dst[e]], 1);
}

// single-block exclusive scan over 20000 counts (1024 threads x 20 chunk)
__global__ void scan_kernel() {
    __shared__ int s[1024];
    const int CH = 20;
    int tid = threadIdx.x;
    int start = tid * CH;
    int lsum = 0;
    for (int i = 0; i < CH; i++) {
        int idx = start + i;
        if (idx < NN) lsum += g_cnt[idx];
    }
    s[tid] = lsum;
    __syncthreads();
    for (int o = 1; o < 1024; o <<= 1) {
        int v = (tid >= o) ? s[tid - o] : 0;
        __syncthreads();
        s[tid] += v;
        __syncthreads();
    }
    int run = s[tid] - lsum;
    for (int i = 0; i < CH; i++) {
        int idx = start + i;
        if (idx < NN) {
            g_off[idx] = run;
            g_cur[idx] = run;
            run += g_cnt[idx];
        }
    }
}

__global__ void fill_kernel(const int* __restrict__ dst) {
    int e = blockIdx.x * blockDim.x + threadIdx.x;
    if (e < EE) {
        int pos = atomicAdd(&g_cur[dst[e]], 1);
        g_perm[pos] = e;
    }
}

// ---------------- small precomputes ---------------------------------------
// v[d,k] = sum_h W_enc[d, k*H+h] * attn_l[k,h]
__global__ void v_kernel(const float* __restrict__ W_enc,
                         const float* __restrict__ attn_l) {
    int i = threadIdx.x;          // 1024 threads = 128*8
    int d = i >> 3, k = i & 7;
    float s = 0.f;
    #pragma unroll 8
    for (int h = 0; h < HH; h++)
        s += W_enc[(size_t)d * KHD + k * HH + h] * attn_l[k * HH + h];
    g_v[d * KK + k] = s;
}

// er[n,k] = sum_d node_feat[n,d] * W_r[k,d]   (one warp per node)
__global__ void er_kernel(const float* __restrict__ nf,
                          const float* __restrict__ W_r) {
    int w = threadIdx.x >> 5;
    int lane = threadIdx.x & 31;
    int n = blockIdx.x * 8 + w;
    if (n >= NN) return;
    const float* row = nf + (size_t)n * DD;
    float a0 = row[lane], a1 = row[lane + 32], a2 = row[lane + 64], a3 = row[lane + 96];
    #pragma unroll
    for (int k = 0; k < KK; k++) {
        const float* wr = W_r + k * DD;
        float v = a0 * wr[lane] + a1 * wr[lane + 32] + a2 * wr[lane + 64] + a3 * wr[lane + 96];
        #pragma unroll
        for (int o = 16; o > 0; o >>= 1) v += __shfl_xor_sync(0xffffffffu, v, o);
        if (lane == 0) g_er[n * KK + k] = v;
    }
}

// ---------------- edge pass (warp-per-edge, float4, reg-resident v) --------
// Lane l owns dims 4l..4l+3. Per edge: 3x LDG.128 (the three metapath rows),
// mean -> STG.128 into g_x, 32 FFMA against register-resident v, then a
// 9-shuffle value-folding butterfly yields all 8 logits (lane&3==0 lanes own
// k = bits{4,3,2} of lane). Persistent grid-stride so the v-register load
// amortizes.
__global__ __launch_bounds__(256) void edge_kernel(const float4* __restrict__ ef4,
                                                   const int* __restrict__ dst) {
    int lane = threadIdx.x & 31;
    int gw = (blockIdx.x * blockDim.x + threadIdx.x) >> 5;
    int nw = (gridDim.x * blockDim.x) >> 5;

    // v registers: vv0[dd] = v[4*lane+dd][k=0..3], vv1[dd] = v[4*lane+dd][k=4..7]
    const float4* gv4 = (const float4*)g_v;
    float4 vv0[4], vv1[4];
    #pragma unroll
    for (int dd = 0; dd < 4; dd++) {
        vv0[dd] = gv4[(4 * lane + dd) * 2 + 0];
        vv1[dd] = gv4[(4 * lane + dd) * 2 + 1];
    }
    int b4 = (lane >> 4) & 1, b3 = (lane >> 3) & 1, b2 = (lane >> 2) & 1;
    int myk = b4 * 4 + b3 * 2 + b2;
    float4* gx4 = (float4*)g_x;
    const float inv3 = 1.0f / 3.0f;

    for (int e = gw; e < EE; e += nw) {
        const float4* base = ef4 + (size_t)e * 96;   // 3*128/4
        float4 r0 = base[lane];
        float4 r1 = base[lane + 32];
        float4 r2 = base[lane + 64];
        int nd = dst[e];                              // uniform broadcast load
        float4 x;
        x.x = (r0.x + r1.x + r2.x) * inv3;
        x.y = (r0.y + r1.y + r2.y) * inv3;
        x.z = (r0.z + r1.z + r2.z) * inv3;
        x.w = (r0.w + r1.w + r2.w) * inv3;
        gx4[(size_t)e * 32 + lane] = x;

        float a[8];
        float xs0 = x.x, xs1 = x.y, xs2 = x.z, xs3 = x.w;
        a[0] = xs0 * vv0[0].x + xs1 * vv0[1].x + xs2 * vv0[2].x + xs3 * vv0[3].x;
        a[1] = xs0 * vv0[0].y + xs1 * vv0[1].y + xs2 * vv0[2].y + xs3 * vv0[3].y;
        a[2] = xs0 * vv0[0].z + xs1 * vv0[1].z + xs2 * vv0[2].z + xs3 * vv0[3].z;
        a[3] = xs0 * vv0[0].w + xs1 * vv0[1].w + xs2 * vv0[2].w + xs3 * vv0[3].w;
        a[4] = xs0 * vv1[0].x + xs1 * vv1[1].x + xs2 * vv1[2].x + xs3 * vv1[3].x;
        a[5] = xs0 * vv1[0].y + xs1 * vv1[1].y + xs2 * vv1[2].y + xs3 * vv1[3].y;
        a[6] = xs0 * vv1[0].z + xs1 * vv1[1].z + xs2 * vv1[2].z + xs3 * vv1[3].z;
        a[7] = xs0 * vv1[0].w + xs1 * vv1[1].w + xs2 * vv1[2].w + xs3 * vv1[3].w;

        // value-folding butterfly: fold k across lane bits 4,3,2
        #pragma unroll
        for (int j = 0; j < 4; j++) {
            float keep = b4 ? a[j + 4] : a[j];
            float send = b4 ? a[j] : a[j + 4];
            a[j] = keep + __shfl_xor_sync(0xffffffffu, send, 16);
        }
        #pragma unroll
        for (int j = 0; j < 2; j++) {
            float keep = b3 ? a[j + 2] : a[j];
            float send = b3 ? a[j] : a[j + 2];
            a[j] = keep + __shfl_xor_sync(0xffffffffu, send, 8);
        }
        {
            float keep = b2 ? a[1] : a[0];
            float send = b2 ? a[0] : a[1];
            a[0] = keep + __shfl_xor_sync(0xffffffffu, send, 4);
        }
        a[0] += __shfl_xor_sync(0xffffffffu, a[0], 2);
        a[0] += __shfl_xor_sync(0xffffffffu, a[0], 1);

        if ((lane & 3) == 0) {
            float z = a[0] + g_er[nd * KK + myk];
            z = (z > 0.f) ? z : 0.01f * z;            // leaky relu
            float wv = __expf(z);                     // shift-free softmax weight
            g_w[e * KK + myk] = wv;
            atomicAdd(&g_denom[nd * KK + myk], wv);
        }
    }
}

// ---------------- per-node weighted x aggregation (warp-per-k) -------------
// 8 warps = 8 heads; lane owns a float4 of dims. Per edge per warp:
// 1 uniform perm load (prefetched), 1 uniform w load, 1 LDG.128, 4 FFMA.
// Tail re-zeroes g_cnt / g_denom for the next graph replay.
__global__ void node_kernel() {
    int n = blockIdx.x;
    int tid = threadIdx.x;
    int k = tid >> 5, lane = tid & 31;

    int deg = g_cnt[n];
    int off = g_off[n];
    float inv = 0.f;
    if (deg > 0) inv = 1.0f / g_denom[n * KK + k];

    const float4* gx4 = (const float4*)g_x;
    float4 acc = make_float4(0.f, 0.f, 0.f, 0.f);

    int e_next = (deg > 0) ? g_perm[off] : 0;
    for (int i = 0; i < deg; i++) {
        int e = e_next;
        if (i + 1 < deg) e_next = g_perm[off + i + 1];
        float w = g_w[e * KK + k] * inv;
        float4 xd = gx4[(size_t)e * 32 + lane];
        acc.x = fmaf(w, xd.x, acc.x);
        acc.y = fmaf(w, xd.y, acc.y);
        acc.z = fmaf(w, xd.z, acc.z);
        acc.w = fmaf(w, xd.w, acc.w);
    }
    float4* gy4 = (float4*)g_y;
    gy4[(size_t)n * 256 + k * 32 + lane] = acc;

    __syncthreads();   // all reads of g_cnt[n]/g_denom done
    if (tid == 0) g_cnt[n] = 0;
    if (tid < KK) g_denom[n * KK + tid] = 0.f;
}

// ---------------- block-diagonal GEMM: out[n,k,:] = y[n,k,:] @ W_k ---------
__global__ void out_kernel(const float* __restrict__ W_enc,
                           float* __restrict__ out) {
    __shared__ float As[64][33];
    __shared__ float Ws[32][65];
    int k = blockIdx.y;
    int n0 = blockIdx.x * 64;
    int tid = threadIdx.x;
    int tx = tid & 15, ty = tid >> 4;
    float c[4][4] = {};

    for (int kk = 0; kk < DD; kk += 32) {
        #pragma unroll
        for (int p = 0; p < 8; p++) {
            int q = tid + 256 * p;
            int row = q >> 5, d = q & 31;
            int n = n0 + row;
            As[row][d] = (n < NN) ? g_y[(size_t)n * (KK * DD) + k * DD + kk + d] : 0.f;
        }
        #pragma unroll
        for (int p = 0; p < 8; p++) {
            int q = tid + 256 * p;
            int d = q >> 6, h = q & 63;
            Ws[d][h] = W_enc[(size_t)(kk + d) * KHD + k * HH + h];
        }
        __syncthreads();
        #pragma unroll
        for (int d = 0; d < 32; d++) {
            float a[4], b[4];
            #pragma unroll
            for (int r = 0; r < 4; r++) a[r] = As[ty * 4 + r][d];
            #pragma unroll
            for (int cc = 0; cc < 4; cc++) b[cc] = Ws[d][tx * 4 + cc];
            #pragma unroll
            for (int r = 0; r < 4; r++)
                #pragma unroll
                for (int cc = 0; cc < 4; cc++) c[r][cc] += a[r] * b[cc];
        }
        __syncthreads();
    }
    #pragma unroll
    for (int r = 0; r < 4; r++) {
        int n = n0 + ty * 4 + r;
        if (n < NN) {
            #pragma unroll
            for (int cc = 0; cc < 4; cc++)
                out[(size_t)n * KHD + k * HH + tx * 4 + cc] = c[r][cc];
        }
    }
}

// ---------------- launch ----------------------------------------------------
// edge_kernel sits at my launch index 3 -> it is the one ncu captures.
extern "C" void kernel_launch(void* const* d_in, const int* in_sizes, int n_in,
                              void* d_out, int out_size) {
    const float* node_feat = (const float*)d_in[0]; // (N,128)
    const float* edge_feat = (const float*)d_in[1]; // (E,3,128)
    const float* W_enc     = (const float*)d_in[2]; // (128,512)
    const float* attn_l    = (const float*)d_in[3]; // (1,8,64)
    const float* W_r       = (const float*)d_in[4]; // (8,128)
    const int*   dst       = (const int*)d_in[5];   // (E,)
    float* out = (float*)d_out;                     // (N,8,64)

    v_kernel<<<1, 1024>>>(W_enc, attn_l);                      // 0
    er_kernel<<<(NN + 7) / 8, 256>>>(node_feat, W_r);          // 1
    count_kernel<<<(EE + 255) / 256, 256>>>(dst);              // 2
    edge_kernel<<<888, 256>>>((const float4*)edge_feat, dst);  // 3  <- profiled
    scan_kernel<<<1, 1024>>>();                                // 4
    fill_kernel<<<(EE + 255) / 256, 256>>>(dst);               // 5
    node_kernel<<<NN, 256>>>();                                // 6
    out_kernel<<<dim3((NN + 63) / 64, 8), 256>>>(W_enc, out);  // 7
}

// round 4
// speedup vs baseline: 1.7682x; 1.3979x over previous
#include <cuda_runtime.h>

// Problem constants (fixed by the dataset)
#define NN 20000
#define EE 320000
#define DD 128
#define KK 8
#define HH 64
#define KHD 512   // K*H

// ---------------- scratch (__device__ globals; no allocations) -------------
// g_cnt and g_denom are zeroed at module load and re-zeroed at the END of
// node_kernel each run, so every graph replay starts from a clean state.
__device__ float g_x[(size_t)EE * DD];      // mean edge features (E,128)
__device__ float g_w[EE * KK];              // exp(leakyrelu(logit))
__device__ float g_er[NN * KK];             // node_feat @ W_r^T
__device__ float g_v[DD * KK];              // W_enc folded with attn_l
__device__ float g_denom[NN * KK];          // softmax denominators
__device__ float g_y[(size_t)NN * KK * DD]; // per-node weighted x sums (N,8,128)
__device__ int   g_cnt[NN];
__device__ int   g_off[NN];
__device__ int   g_cur[NN];
__device__ int   g_perm[EE];

// ---------------- CSR build ------------------------------------------------
__global__ void count_kernel(const int* __restrict__ dst) {
    int e = blockIdx.x * blockDim.x + threadIdx.x;
    if (e < EE) atomicAdd(&g_cnt[dst[e]], 1);
}

// single-block exclusive scan over 20000 counts (1024 threads x 20 chunk)
__global__ void scan_kernel() {
    __shared__ int s[1024];
    const int CH = 20;
    int tid = threadIdx.x;
    int start = tid * CH;
    int lsum = 0;
    for (int i = 0; i < CH; i++) {
        int idx = start + i;
        if (idx < NN) lsum += g_cnt[idx];
    }
    s[tid] = lsum;
    __syncthreads();
    for (int o = 1; o < 1024; o <<= 1) {
        int v = (tid >= o) ? s[tid - o] : 0;
        __syncthreads();
        s[tid] += v;
        __syncthreads();
    }
    int run = s[tid] - lsum;
    for (int i = 0; i < CH; i++) {
        int idx = start + i;
        if (idx < NN) {
            g_off[idx] = run;
            g_cur[idx] = run;
            run += g_cnt[idx];
        }
    }
}

__global__ void fill_kernel(const int* __restrict__ dst) {
    int e = blockIdx.x * blockDim.x + threadIdx.x;
    if (e < EE) {
        int pos = atomicAdd(&g_cur[dst[e]], 1);
        g_perm[pos] = e;
    }
}

// ---------------- small precomputes ---------------------------------------
// v[d,k] = sum_h W_enc[d, k*H+h] * attn_l[k,h]
__global__ void v_kernel(const float* __restrict__ W_enc,
                         const float* __restrict__ attn_l) {
    int i = threadIdx.x;          // 1024 threads = 128*8
    int d = i >> 3, k = i & 7;
    float s = 0.f;
    #pragma unroll 8
    for (int h = 0; h < HH; h++)
        s += W_enc[(size_t)d * KHD + k * HH + h] * attn_l[k * HH + h];
    g_v[d * KK + k] = s;
}

// er[n,k] = sum_d node_feat[n,d] * W_r[k,d]   (one warp per node)
__global__ void er_kernel(const float* __restrict__ nf,
                          const float* __restrict__ W_r) {
    int w = threadIdx.x >> 5;
    int lane = threadIdx.x & 31;
    int n = blockIdx.x * 8 + w;
    if (n >= NN) return;
    const float* row = nf + (size_t)n * DD;
    float a0 = row[lane], a1 = row[lane + 32], a2 = row[lane + 64], a3 = row[lane + 96];
    #pragma unroll
    for (int k = 0; k < KK; k++) {
        const float* wr = W_r + k * DD;
        float v = a0 * wr[lane] + a1 * wr[lane + 32] + a2 * wr[lane + 64] + a3 * wr[lane + 96];
        #pragma unroll
        for (int o = 16; o > 0; o >>= 1) v += __shfl_xor_sync(0xffffffffu, v, o);
        if (lane == 0) g_er[n * KK + k] = v;
    }
}

// ---------------- edge pass (warp-per-edge, float4, reg v, 2-deep pipe) ----
// Lane l owns dims 4l..4l+3. Software pipeline: the NEXT edge's three rows
// (+dst) are issued at the top of each iteration, so they are in flight while
// the current edge's mean/logits/butterfly execute. MLP/warp ~= 6.
__global__ __launch_bounds__(128) void edge_kernel(const float4* __restrict__ ef4,
                                                   const int* __restrict__ dst) {
    int lane = threadIdx.x & 31;
    int gw = (blockIdx.x * blockDim.x + threadIdx.x) >> 5;
    int nw = (gridDim.x * blockDim.x) >> 5;

    // v registers: vv0[dd] = v[4*lane+dd][k=0..3], vv1[dd] = v[4*lane+dd][k=4..7]
    const float4* gv4 = (const float4*)g_v;
    float4 vv0[4], vv1[4];
    #pragma unroll
    for (int dd = 0; dd < 4; dd++) {
        vv0[dd] = gv4[(4 * lane + dd) * 2 + 0];
        vv1[dd] = gv4[(4 * lane + dd) * 2 + 1];
    }
    int b4 = (lane >> 4) & 1, b3 = (lane >> 3) & 1, b2 = (lane >> 2) & 1;
    int myk = b4 * 4 + b3 * 2 + b2;
    float4* gx4 = (float4*)g_x;
    const float inv3 = 1.0f / 3.0f;

    if (gw >= EE) return;
    // prologue loads for first edge
    const float4* base = ef4 + (size_t)gw * 96;
    float4 c0 = base[lane];
    float4 c1 = base[lane + 32];
    float4 c2 = base[lane + 64];
    int cnd = dst[gw];

    for (int e = gw; e < EE; e += nw) {
        int e2 = e + nw;
        int ep = (e2 < EE) ? e2 : e;
        // issue next edge's loads NOW (consumed at loop bottom)
        const float4* nbase = ef4 + (size_t)ep * 96;
        float4 n0 = nbase[lane];
        float4 n1 = nbase[lane + 32];
        float4 n2 = nbase[lane + 64];
        int nnd = dst[ep];

        float4 x;
        x.x = (c0.x + c1.x + c2.x) * inv3;
        x.y = (c0.y + c1.y + c2.y) * inv3;
        x.z = (c0.z + c1.z + c2.z) * inv3;
        x.w = (c0.w + c1.w + c2.w) * inv3;
        gx4[(size_t)e * 32 + lane] = x;

        float a[8];
        a[0] = x.x * vv0[0].x + x.y * vv0[1].x + x.z * vv0[2].x + x.w * vv0[3].x;
        a[1] = x.x * vv0[0].y + x.y * vv0[1].y + x.z * vv0[2].y + x.w * vv0[3].y;
        a[2] = x.x * vv0[0].z + x.y * vv0[1].z + x.z * vv0[2].z + x.w * vv0[3].z;
        a[3] = x.x * vv0[0].w + x.y * vv0[1].w + x.z * vv0[2].w + x.w * vv0[3].w;
        a[4] = x.x * vv1[0].x + x.y * vv1[1].x + x.z * vv1[2].x + x.w * vv1[3].x;
        a[5] = x.x * vv1[0].y + x.y * vv1[1].y + x.z * vv1[2].y + x.w * vv1[3].y;
        a[6] = x.x * vv1[0].z + x.y * vv1[1].z + x.z * vv1[2].z + x.w * vv1[3].z;
        a[7] = x.x * vv1[0].w + x.y * vv1[1].w + x.z * vv1[2].w + x.w * vv1[3].w;

        // value-folding butterfly: fold k across lane bits 4,3,2
        #pragma unroll
        for (int j = 0; j < 4; j++) {
            float keep = b4 ? a[j + 4] : a[j];
            float send = b4 ? a[j] : a[j + 4];
            a[j] = keep + __shfl_xor_sync(0xffffffffu, send, 16);
        }
        #pragma unroll
        for (int j = 0; j < 2; j++) {
            float keep = b3 ? a[j + 2] : a[j];
            float send = b3 ? a[j] : a[j + 2];
            a[j] = keep + __shfl_xor_sync(0xffffffffu, send, 8);
        }
        {
            float keep = b2 ? a[1] : a[0];
            float send = b2 ? a[0] : a[1];
            a[0] = keep + __shfl_xor_sync(0xffffffffu, send, 4);
        }
        a[0] += __shfl_xor_sync(0xffffffffu, a[0], 2);
        a[0] += __shfl_xor_sync(0xffffffffu, a[0], 1);

        if ((lane & 3) == 0) {
            float z = a[0] + g_er[cnd * KK + myk];
            z = (z > 0.f) ? z : 0.01f * z;            // leaky relu
            float wv = __expf(z);                     // shift-free softmax weight
            g_w[e * KK + myk] = wv;
            atomicAdd(&g_denom[cnd * KK + myk], wv);
        }

        c0 = n0; c1 = n1; c2 = n2; cnd = nnd;
    }
}

// ---------------- per-node weighted x aggregation (warp-per-NODE) ----------
// One warp per node. Lane owns dims 4l..4l+3; all 8 heads accumulate in
// registers (acc[8] float4). Per edge: 1 LDG.128 (x row, read ONCE) +
// 2 uniform float4 loads (the 8 weights) + 32 FFMA. 1/denom applied once
// after the loop. 2-deep prefetch. Tail re-zeroes g_cnt / g_denom.
__global__ __launch_bounds__(256) void node_kernel() {
    int warp = threadIdx.x >> 5;
    int lane = threadIdx.x & 31;
    int n = blockIdx.x * 8 + warp;
    if (n >= NN) return;

    int deg = g_cnt[n];
    int off = g_off[n];
    const float4* gx4 = (const float4*)g_x;
    const float4* gw4 = (const float4*)g_w;

    float4 acc[8];
    #pragma unroll
    for (int k = 0; k < 8; k++) acc[k] = make_float4(0.f, 0.f, 0.f, 0.f);

    if (deg > 0) {
        int e = g_perm[off];
        float4 xd = gx4[(size_t)e * 32 + lane];
        float4 wa = gw4[e * 2], wb = gw4[e * 2 + 1];
        for (int i = 0; i < deg; i++) {
            int e2 = (i + 1 < deg) ? g_perm[off + i + 1] : e;
            float4 xn = gx4[(size_t)e2 * 32 + lane];
            float4 wan = gw4[e2 * 2], wbn = gw4[e2 * 2 + 1];

            acc[0].x = fmaf(wa.x, xd.x, acc[0].x);
            acc[0].y = fmaf(wa.x, xd.y, acc[0].y);
            acc[0].z = fmaf(wa.x, xd.z, acc[0].z);
            acc[0].w = fmaf(wa.x, xd.w, acc[0].w);
            acc[1].x = fmaf(wa.y, xd.x, acc[1].x);
            acc[1].y = fmaf(wa.y, xd.y, acc[1].y);
            acc[1].z = fmaf(wa.y, xd.z, acc[1].z);
            acc[1].w = fmaf(wa.y, xd.w, acc[1].w);
            acc[2].x = fmaf(wa.z, xd.x, acc[2].x);
            acc[2].y = fmaf(wa.z, xd.y, acc[2].y);
            acc[2].z = fmaf(wa.z, xd.z, acc[2].z);
            acc[2].w = fmaf(wa.z, xd.w, acc[2].w);
            acc[3].x = fmaf(wa.w, xd.x, acc[3].x);
            acc[3].y = fmaf(wa.w, xd.y, acc[3].y);
            acc[3].z = fmaf(wa.w, xd.z, acc[3].z);
            acc[3].w = fmaf(wa.w, xd.w, acc[3].w);
            acc[4].x = fmaf(wb.x, xd.x, acc[4].x);
            acc[4].y = fmaf(wb.x, xd.y, acc[4].y);
            acc[4].z = fmaf(wb.x, xd.z, acc[4].z);
            acc[4].w = fmaf(wb.x, xd.w, acc[4].w);
            acc[5].x = fmaf(wb.y, xd.x, acc[5].x);
            acc[5].y = fmaf(wb.y, xd.y, acc[5].y);
            acc[5].z = fmaf(wb.y, xd.z, acc[5].z);
            acc[5].w = fmaf(wb.y, xd.w, acc[5].w);
            acc[6].x = fmaf(wb.z, xd.x, acc[6].x);
            acc[6].y = fmaf(wb.z, xd.y, acc[6].y);
            acc[6].z = fmaf(wb.z, xd.z, acc[6].z);
            acc[6].w = fmaf(wb.z, xd.w, acc[6].w);
            acc[7].x = fmaf(wb.w, xd.x, acc[7].x);
            acc[7].y = fmaf(wb.w, xd.y, acc[7].y);
            acc[7].z = fmaf(wb.w, xd.z, acc[7].z);
            acc[7].w = fmaf(wb.w, xd.w, acc[7].w);

            xd = xn; wa = wan; wb = wbn;
        }
    }

    // per-head 1/denom, applied once
    const float4* dn4 = (const float4*)(g_denom + n * KK);
    float4 d0 = dn4[0], d1 = dn4[1];
    float inv[8];
    inv[0] = (deg > 0) ? __frcp_rn(d0.x) : 0.f;
    inv[1] = (deg > 0) ? __frcp_rn(d0.y) : 0.f;
    inv[2] = (deg > 0) ? __frcp_rn(d0.z) : 0.f;
    inv[3] = (deg > 0) ? __frcp_rn(d0.w) : 0.f;
    inv[4] = (deg > 0) ? __frcp_rn(d1.x) : 0.f;
    inv[5] = (deg > 0) ? __frcp_rn(d1.y) : 0.f;
    inv[6] = (deg > 0) ? __frcp_rn(d1.z) : 0.f;
    inv[7] = (deg > 0) ? __frcp_rn(d1.w) : 0.f;

    float4* gy4 = (float4*)g_y;
    #pragma unroll
    for (int k = 0; k < 8; k++) {
        float4 o;
        o.x = acc[k].x * inv[k];
        o.y = acc[k].y * inv[k];
        o.z = acc[k].z * inv[k];
        o.w = acc[k].w * inv[k];
        gy4[(size_t)n * 256 + k * 32 + lane] = o;
    }

    __syncwarp();   // all lanes finished reading g_cnt/g_denom
    if (lane == 0) g_cnt[n] = 0;
    if (lane < KK) g_denom[n * KK + lane] = 0.f;
}

// ---------------- block-diagonal GEMM: out[n,k,:] = y[n,k,:] @ W_k ---------
__global__ void out_kernel(const float* __restrict__ W_enc,
                           float* __restrict__ out) {
    __shared__ float As[64][33];
    __shared__ float Ws[32][65];
    int k = blockIdx.y;
    int n0 = blockIdx.x * 64;
    int tid = threadIdx.x;
    int tx = tid & 15, ty = tid >> 4;
    float c[4][4] = {};

    for (int kk = 0; kk < DD; kk += 32) {
        #pragma unroll
        for (int p = 0; p < 8; p++) {
            int q = tid + 256 * p;
            int row = q >> 5, d = q & 31;
            int n = n0 + row;
            As[row][d] = (n < NN) ? g_y[(size_t)n * (KK * DD) + k * DD + kk + d] : 0.f;
        }
        #pragma unroll
        for (int p = 0; p < 8; p++) {
            int q = tid + 256 * p;
            int d = q >> 6, h = q & 63;
            Ws[d][h] = W_enc[(size_t)(kk + d) * KHD + k * HH + h];
        }
        __syncthreads();
        #pragma unroll
        for (int d = 0; d < 32; d++) {
            float a[4], b[4];
            #pragma unroll
            for (int r = 0; r < 4; r++) a[r] = As[ty * 4 + r][d];
            #pragma unroll
            for (int cc = 0; cc < 4; cc++) b[cc] = Ws[d][tx * 4 + cc];
            #pragma unroll
            for (int r = 0; r < 4; r++)
                #pragma unroll
                for (int cc = 0; cc < 4; cc++) c[r][cc] += a[r] * b[cc];
        }
        __syncthreads();
    }
    #pragma unroll
    for (int r = 0; r < 4; r++) {
        int n = n0 + ty * 4 + r;
        if (n < NN) {
            #pragma unroll
            for (int cc = 0; cc < 4; cc++)
                out[(size_t)n * KHD + k * HH + tx * 4 + cc] = c[r][cc];
        }
    }
}

// ---------------- launch ----------------------------------------------------
// edge_kernel sits at my launch index 3 -> it is the one ncu captures.
extern "C" void kernel_launch(void* const* d_in, const int* in_sizes, int n_in,
                              void* d_out, int out_size) {
    const float* node_feat = (const float*)d_in[0]; // (N,128)
    const float* edge_feat = (const float*)d_in[1]; // (E,3,128)
    const float* W_enc     = (const float*)d_in[2]; // (128,512)
    const float* attn_l    = (const float*)d_in[3]; // (1,8,64)
    const float* W_r       = (const float*)d_in[4]; // (8,128)
    const int*   dst       = (const int*)d_in[5];   // (E,)
    float* out = (float*)d_out;                     // (N,8,64)

    v_kernel<<<1, 1024>>>(W_enc, attn_l);                       // 0
    er_kernel<<<(NN + 7) / 8, 256>>>(node_feat, W_r);           // 1
    count_kernel<<<(EE + 255) / 256, 256>>>(dst);               // 2
    edge_kernel<<<1480, 128>>>((const float4*)edge_feat, dst);  // 3  <- profiled
    scan_kernel<<<1, 1024>>>();                                 // 4
    fill_kernel<<<(EE + 255) / 256, 256>>>(dst);                // 5
    node_kernel<<<(NN + 7) / 8, 256>>>();                       // 6
    out_kernel<<<dim3((NN + 63) / 64, 8), 256>>>(W_enc, out);   // 7
}